// round 8
// baseline (speedup 1.0000x reference)
#include <cuda_runtime.h>
#include <cstdint>

// ---------------------------------------------------------------------------
// Problem constants
// ---------------------------------------------------------------------------
static constexpr int H = 160, W = 288, HO = 80, WO = 144;
static constexpr int NPIX = HO * WO;     // 11520
static constexpr int DMAX = 24;          // MAXDISP / (4*S)

// ---------------------------------------------------------------------------
// Scratch (__device__ globals; no cudaMalloc allowed)
// ---------------------------------------------------------------------------
__device__ float g_y_gwc[4 * 192 * NPIX];   // conv1+bn+lrelu output, gwc branch
__device__ float g_g8x[4 * 96 * NPIX];      // downsampled gwc feature
__device__ float g_c8x[4 * 12 * NPIX];      // downsampled concat feature
__device__ float g_mask[4 * 144 * NPIX];    // softmaxed gwc masks [b][g*9+k][px]
// conv1 weights as ready-made m16n8k8 A-fragments:
// [seg = (chunk*9+tap)*4+ks][mtile 0..11][lane 0..31] float4 {a0,a1,a2,a3}
__device__ float4 g_wf[108 * 12 * 32];
// mask conv2 weights as A-fragments: [kstep 0..23][mtile 0..8][lane] float4
__device__ float4 g_w2f[24 * 9 * 32];

// ---------------------------------------------------------------------------
// helpers
// ---------------------------------------------------------------------------
__device__ __forceinline__ uint32_t cvt_tf32(float v) {
  uint32_t t; asm("cvt.rna.tf32.f32 %0, %1;" : "=r"(t) : "f"(v)); return t;
}
__device__ __forceinline__ float cvt_tf32f(float v) {
  return __uint_as_float(cvt_tf32(v));
}
__device__ __forceinline__ void mma8(float* d, const uint32_t* a,
                                     uint32_t b0, uint32_t b1) {
  asm volatile(
      "mma.sync.aligned.m16n8k8.row.col.f32.tf32.tf32.f32 "
      "{%0,%1,%2,%3}, {%4,%5,%6,%7}, {%8,%9}, {%0,%1,%2,%3};"
      : "+f"(d[0]), "+f"(d[1]), "+f"(d[2]), "+f"(d[3])
      : "r"(a[0]), "r"(a[1]), "r"(a[2]), "r"(a[3]), "r"(b0), "r"(b1));
}

// ---------------------------------------------------------------------------
// Weight prep (single launch): conv1 + mask-conv2 fragments, tf32 float4
// ---------------------------------------------------------------------------
__global__ void prep_all(const float* __restrict__ w, const float* __restrict__ w2) {
  int idx = blockIdx.x * 256 + threadIdx.x;
  if (idx < 108 * 12 * 32) {
    int lane = idx & 31;
    int mt   = (idx >> 5) % 12;
    int seg  = idx / (12 * 32);
    int ks   = seg & 3;
    int tile = seg >> 2;            // chunk*9 + tap
    int chunk = tile / 9, tap = tile % 9;
    int lq = lane >> 2, lr = lane & 3;
    int ic = chunk * 32 + ks * 8 + lr;
    int m0 = mt * 16 + lq;
    float4 f;
    f.x = cvt_tf32f(w[((size_t)m0 * 96 + ic) * 9 + tap]);
    f.y = cvt_tf32f(w[((size_t)(m0 + 8) * 96 + ic) * 9 + tap]);
    f.z = cvt_tf32f(w[((size_t)m0 * 96 + ic + 4) * 9 + tap]);
    f.w = cvt_tf32f(w[((size_t)(m0 + 8) * 96 + ic + 4) * 9 + tap]);
    g_wf[idx] = f;
  } else {
    int j = idx - 108 * 12 * 32;
    if (j >= 24 * 9 * 32) return;
    int lane = j & 31;
    int mt   = (j >> 5) % 9;
    int ks   = j / (9 * 32);
    int lq = lane >> 2, lr = lane & 3;
    int k  = ks * 8 + lr;
    int m0 = mt * 16 + lq;
    float4 f;
    f.x = cvt_tf32f(w2[(size_t)m0 * 192 + k]);
    f.y = cvt_tf32f(w2[(size_t)(m0 + 8) * 192 + k]);
    f.z = cvt_tf32f(w2[(size_t)m0 * 192 + k + 4]);
    f.w = cvt_tf32f(w2[(size_t)(m0 + 8) * 192 + k + 4]);
    g_w2f[j] = f;
  }
}

// ---------------------------------------------------------------------------
// TF32 mma.sync implicit-GEMM conv3x3 s2 p1 + BN + LeakyReLU  (96 -> 192)
// Block: 256 threads (8 warps, 2M x 4N). Tile: 64 oc x 128 px (8 rows x 16 cols).
// ---------------------------------------------------------------------------
static constexpr int RAW_WORDS = 17 * 32 * 33;           // 17952 floats
static constexpr int SC_OFF_B  = RAW_WORDS * 4;          // 71808
static constexpr int CONV_SMEM = SC_OFF_B + 2 * 64 * 4;  // 72320

__global__ __launch_bounds__(256, 2)
void conv_mma(const float* __restrict__ x,
              const float* __restrict__ bg, const float* __restrict__ bb,
              const float* __restrict__ bm, const float* __restrict__ bv,
              float* __restrict__ y) {
  extern __shared__ char smem[];
  float* raw = (float*)smem;
  float* sc  = (float*)(smem + SC_OFF_B);
  float* ssh = sc + 64;

  const int tid  = threadIdx.x;
  const int lane = tid & 31;
  const int wid  = tid >> 5;
  const int wm = wid >> 2;          // 0..1
  const int wn = wid & 3;           // 0..3
  const int lq = lane >> 2;         // 0..7
  const int lr = lane & 3;          // 0..3
  const int bx = blockIdx.x, by = blockIdx.y;
  const int b   = blockIdx.z / 3;
  const int ocb = blockIdx.z % 3;
  const int ihb = by * 16 - 1;
  const int iwb = bx * 32 - 1;

  if (tid < 64) {
    const int oc = ocb * 64 + tid;
    const float s = bg[oc] * rsqrtf(bv[oc] + 1e-5f);
    sc[tid]  = s;
    ssh[tid] = bb[oc] - bm[oc] * s;
  }

  float acc[2][4][4];
#pragma unroll
  for (int mi = 0; mi < 2; ++mi)
#pragma unroll
    for (int j = 0; j < 4; ++j)
#pragma unroll
      for (int q = 0; q < 4; ++q) acc[mi][j][q] = 0.f;

  for (int chunk = 0; chunk < 3; ++chunk) {
    __syncthreads();
    // stage raw input (pre-converted to tf32): raw[(ri*32+ic)*33 + ci]
    for (int e = tid; e < 17 * 33 * 32; e += 256) {
      const int ci = e % 33;
      const int t  = e / 33;
      const int ic = t & 31;
      const int ri = t >> 5;
      const int ih = ihb + ri, iw = iwb + ci;
      float v = 0.f;
      if (ih >= 0 && iw >= 0)
        v = x[((size_t)(b * 96 + chunk * 32 + ic) * H + ih) * W + iw];
      raw[(ri * 32 + ic) * 33 + ci] = cvt_tf32f(v);
    }
    __syncthreads();

    for (int tap = 0; tap < 9; ++tap) {
      const int tile = chunk * 9 + tap;
      float4 A4[4][2];
#pragma unroll
      for (int ks = 0; ks < 4; ++ks)
#pragma unroll
        for (int mi = 0; mi < 2; ++mi)
          A4[ks][mi] = __ldg(&g_wf[((size_t)(tile * 4 + ks) * 12 +
                                    ocb * 4 + wm * 2 + mi) * 32 + lane]);
      const int kh = tap / 3, kw = tap % 3;
      int bofs[4];
#pragma unroll
      for (int j = 0; j < 4; ++j) {
        const int ri = 4 * wn + 2 * (j >> 1) + kh;
        const int ci = 16 * (j & 1) + 2 * lq + kw;
        bofs[j] = ri * (32 * 33) + ci;
      }
#pragma unroll
      for (int ks = 0; ks < 4; ++ks) {
        const uint32_t* a0 = reinterpret_cast<const uint32_t*>(&A4[ks][0]);
        const uint32_t* a1 = reinterpret_cast<const uint32_t*>(&A4[ks][1]);
#pragma unroll
        for (int j = 0; j < 4; ++j) {
          const int base = bofs[j] + (ks * 8 + lr) * 33;
          const uint32_t b0 = __float_as_uint(raw[base]);
          const uint32_t b1 = __float_as_uint(raw[base + 4 * 33]);
          mma8(acc[0][j], a0, b0, b1);
          mma8(acc[1][j], a1, b0, b1);
        }
      }
    }
  }

  // epilogue: BN + LeakyReLU, float2 stores into NCHW y
#pragma unroll
  for (int mi = 0; mi < 2; ++mi) {
    const int oc_l0 = wm * 32 + mi * 16 + lq;
    const int oc_l1 = oc_l0 + 8;
    const float s0 = sc[oc_l0], h0 = ssh[oc_l0];
    const float s1 = sc[oc_l1], h1 = ssh[oc_l1];
    const int oc0 = ocb * 64 + oc_l0;
#pragma unroll
    for (int j = 0; j < 4; ++j) {
      const int oh = by * 8 + wn * 2 + (j >> 1);
      const int ow = bx * 16 + (j & 1) * 8 + 2 * lr;
      float v0 = acc[mi][j][0] * s0 + h0;
      float v1 = acc[mi][j][1] * s0 + h0;
      float v2 = acc[mi][j][2] * s1 + h1;
      float v3 = acc[mi][j][3] * s1 + h1;
      v0 = (v0 >= 0.f) ? v0 : 0.1f * v0;
      v1 = (v1 >= 0.f) ? v1 : 0.1f * v1;
      v2 = (v2 >= 0.f) ? v2 : 0.1f * v2;
      v3 = (v3 >= 0.f) ? v3 : 0.1f * v3;
      *(float2*)(y + ((size_t)(b * 192 + oc0)     * HO + oh) * WO + ow) =
          make_float2(v0, v1);
      *(float2*)(y + ((size_t)(b * 192 + oc0 + 8) * HO + oh) * WO + ow) =
          make_float2(v2, v3);
    }
  }
}

// ---------------------------------------------------------------------------
// Mask GEMM (144x192 via mma) + softmax -> normalized masks to gmem.
// One block per (h row, batch): 288 threads (9 warps, 3M x 3N).
// ---------------------------------------------------------------------------
static constexpr int SY_STRIDE  = 168;                 // conflict-free b-frags
static constexpr int SL_STRIDE  = 145;
static constexpr int MASK_SMEM  = 144 * SL_STRIDE * 4; // 83520 (> sy chunk)

__global__ __launch_bounds__(288, 2)
void mask_mma(const float* __restrict__ y, float* __restrict__ mask) {
  extern __shared__ float smf[];
  float* sy   = smf;                      // [64][SY_STRIDE] per k-chunk
  float* slog = smf;                      // [144][SL_STRIDE] (aliases sy)

  const int tid  = threadIdx.x;
  const int lane = tid & 31;
  const int wid  = tid >> 5;              // 0..8
  const int wm = wid / 3, wn = wid % 3;
  const int lq = lane >> 2, lr = lane & 3;
  const int h = blockIdx.x, b = blockIdx.y;

  float facc[3][6][4];
#pragma unroll
  for (int mtl = 0; mtl < 3; ++mtl)
#pragma unroll
    for (int ntl = 0; ntl < 6; ++ntl)
#pragma unroll
      for (int q = 0; q < 4; ++q) facc[mtl][ntl][q] = 0.f;

  for (int kc = 0; kc < 3; ++kc) {
    __syncthreads();
    for (int idx = tid; idx < 64 * 144; idx += 288) {
      const int cc = idx / 144, px = idx - cc * 144;
      sy[cc * SY_STRIDE + px] =
          cvt_tf32f(y[((size_t)(b * 192 + kc * 64 + cc)) * NPIX + h * 144 + px]);
    }
    __syncthreads();

#pragma unroll
    for (int ks = 0; ks < 8; ++ks) {
      const int kseg = kc * 8 + ks;
      float4 af[3];
#pragma unroll
      for (int mtl = 0; mtl < 3; ++mtl)
        af[mtl] = __ldg(&g_w2f[((size_t)kseg * 9 + wm * 3 + mtl) * 32 + lane]);
#pragma unroll
      for (int ntl = 0; ntl < 6; ++ntl) {
        const int n0 = (wn * 6 + ntl) * 8;
        const uint32_t b0 = __float_as_uint(sy[(ks * 8 + lr) * SY_STRIDE + n0 + lq]);
        const uint32_t b1 = __float_as_uint(sy[(ks * 8 + lr + 4) * SY_STRIDE + n0 + lq]);
#pragma unroll
        for (int mtl = 0; mtl < 3; ++mtl)
          mma8(facc[mtl][ntl], reinterpret_cast<const uint32_t*>(&af[mtl]), b0, b1);
      }
    }
  }

  __syncthreads();   // done reading sy; safe to overwrite with slog
#pragma unroll
  for (int mtl = 0; mtl < 3; ++mtl) {
    const int m0 = (wm * 3 + mtl) * 16;
#pragma unroll
    for (int ntl = 0; ntl < 6; ++ntl) {
      const int n0 = (wn * 6 + ntl) * 8 + 2 * lr;
      slog[(m0 + lq)     * SL_STRIDE + n0]     = facc[mtl][ntl][0];
      slog[(m0 + lq)     * SL_STRIDE + n0 + 1] = facc[mtl][ntl][1];
      slog[(m0 + lq + 8) * SL_STRIDE + n0]     = facc[mtl][ntl][2];
      slog[(m0 + lq + 8) * SL_STRIDE + n0 + 1] = facc[mtl][ntl][3];
    }
  }
  __syncthreads();

  // softmax + write masks: thread owns px = tid%144; groups g = tid/144 + 2*i
  const int px = tid % 144;
  const int gh = tid / 144;          // 0 or 1
#pragma unroll 1
  for (int i = 0; i < 8; ++i) {
    const int g = gh + 2 * i;
    float m9[9];
#pragma unroll
    for (int k = 0; k < 9; ++k) m9[k] = slog[(g * 9 + k) * SL_STRIDE + px];
    float mx = m9[0];
#pragma unroll
    for (int k = 1; k < 9; ++k) mx = fmaxf(mx, m9[k]);
    float sum = 0.f;
#pragma unroll
    for (int k = 0; k < 9; ++k) { m9[k] = __expf(m9[k] - mx); sum += m9[k]; }
    const float inv = 1.f / sum;
#pragma unroll
    for (int k = 0; k < 9; ++k)
      mask[((size_t)(b * 16 + g) * 9 + k) * NPIX + h * 144 + px] = m9[k] * inv;
  }
}

// ---------------------------------------------------------------------------
// Combine: out[b][cc*16+g][h][px] = sum_k mask[b][g*9+k][h][px] * x_window.
// Grid (40 h-pairs, 16 g, 4 b) = 2560 blocks, 288 thr, 10.4 KB smem -> high occ.
// ---------------------------------------------------------------------------
__global__ __launch_bounds__(288)
void combine_gwc(const float* __restrict__ x, const float* __restrict__ mask,
                 float* __restrict__ out) {
  __shared__ float smk[2 * 9 * 144];
  const int tid = threadIdx.x;
  const int g = blockIdx.y, b = blockIdx.z;
  const int h0 = blockIdx.x * 2;

  const size_t mbase = ((size_t)(b * 16 + g) * 9) * NPIX + h0 * 144;
  for (int i = tid; i < 2 * 9 * 144; i += 288) {
    const int hloc = i / (9 * 144);
    const int rem  = i - hloc * (9 * 144);       // k*144 + px
    const int k    = rem / 144;
    const int px   = rem - k * 144;
    smk[i] = mask[mbase + (size_t)k * NPIX + hloc * 144 + px];
  }
  __syncthreads();

  const int px   = tid % 144;
  const int hloc = tid / 144;
  const int h = h0 + hloc;

  float mk[9];
#pragma unroll
  for (int k = 0; k < 9; ++k) mk[k] = smk[hloc * 9 * 144 + k * 144 + px];

#pragma unroll 2
  for (int cc = 0; cc < 6; ++cc) {
    const int c = cc * 16 + g;
    const float* xb = x + (size_t)(b * 96 + c) * H * W;
    float s = 0.f;
#pragma unroll
    for (int kh = 0; kh < 3; ++kh) {
      const int ih = 2 * h - 1 + kh;
      if ((unsigned)ih >= (unsigned)H) continue;
#pragma unroll
      for (int kw = 0; kw < 3; ++kw) {
        const int iw = 2 * px - 1 + kw;
        if ((unsigned)iw >= (unsigned)W) continue;
        s += mk[kh * 3 + kw] * __ldg(&xb[(size_t)ih * W + iw]);
      }
    }
    out[(size_t)(b * 96 + c) * NPIX + h * 144 + px] = s;
  }
}

// ---------------------------------------------------------------------------
// Fully fused cat branch (unchanged from R7)
// ---------------------------------------------------------------------------
static constexpr int CF_SX   = 0;                       // [3][12][292] floats
static constexpr int CF_SY   = 3 * 12 * 292;            // 10512 -> [24][148]
static constexpr int CF_SW1  = CF_SY + 24 * 148;        // [108][24]
static constexpr int CF_SW2  = CF_SW1 + 108 * 24;       // [108][24] (m-major)
static constexpr int CF_SBN  = CF_SW2 + 108 * 24;       // [2][24]
static constexpr int CF_SMEM = (CF_SBN + 48) * 4;       // ~77 KB

__global__ __launch_bounds__(288, 2)
void cat_fused(const float* __restrict__ x, const float* __restrict__ w1,
               const float* __restrict__ bg, const float* __restrict__ bb,
               const float* __restrict__ bm, const float* __restrict__ bv,
               const float* __restrict__ w2, float* __restrict__ out) {
  extern __shared__ float sm[];
  float* sx  = sm + CF_SX;    // [kh][ic][iw+1], zero-padded
  float* sy  = sm + CF_SY;    // [oc][px]
  float* sw1 = sm + CF_SW1;   // [ic*9+tap][oc]
  float* sw2 = sm + CF_SW2;   // [mask][k]
  float* sbn = sm + CF_SBN;

  const int tid = threadIdx.x;
  const int h = blockIdx.x, b = blockIdx.y;

  for (int i = tid; i < 24 * 108; i += 288) {
    const int oc = i / 108, rem = i - oc * 108;   // rem = ic*9 + tap
    sw1[rem * 24 + oc] = w1[i];
  }
  for (int i = tid; i < 108 * 24; i += 288) sw2[i] = w2[i];
  if (tid < 24) {
    const float s = bg[tid] * rsqrtf(bv[tid] + 1e-5f);
    sbn[tid]      = s;
    sbn[24 + tid] = bb[tid] - bm[tid] * s;
  }
  for (int i = tid; i < 3 * 12 * 290; i += 288) {
    const int r  = i / (12 * 290);
    const int rem = i - r * (12 * 290);
    const int c  = rem / 290;
    const int iw = rem - c * 290 - 1;
    const int ih = 2 * h - 1 + r;
    float v = 0.f;
    if ((unsigned)ih < (unsigned)H && (unsigned)iw < (unsigned)W)
      v = x[((size_t)(b * 12 + c) * H + ih) * W + iw];
    sx[(r * 12 + c) * 292 + iw + 1] = v;
  }
  __syncthreads();

  const int px   = tid % 144;
  const int half = tid / 144;

  {
    float acc[12];
#pragma unroll
    for (int o = 0; o < 12; ++o) acc[o] = 0.f;
#pragma unroll 3
    for (int ic = 0; ic < 12; ++ic) {
#pragma unroll
      for (int kh = 0; kh < 3; ++kh) {
#pragma unroll
        for (int kw = 0; kw < 3; ++kw) {
          const float xv = sx[(kh * 12 + ic) * 292 + 2 * px + kw];
          const float* wr = &sw1[(ic * 9 + kh * 3 + kw) * 24 + half * 12];
          const float4 wa = *(const float4*)(wr);
          const float4 wb = *(const float4*)(wr + 4);
          const float4 wc = *(const float4*)(wr + 8);
          acc[0] += xv * wa.x; acc[1] += xv * wa.y;
          acc[2] += xv * wa.z; acc[3] += xv * wa.w;
          acc[4] += xv * wb.x; acc[5] += xv * wb.y;
          acc[6] += xv * wb.z; acc[7] += xv * wb.w;
          acc[8] += xv * wc.x; acc[9] += xv * wc.y;
          acc[10] += xv * wc.z; acc[11] += xv * wc.w;
        }
      }
    }
#pragma unroll
    for (int o = 0; o < 12; ++o) {
      const int oc = half * 12 + o;
      float v = acc[o] * sbn[oc] + sbn[24 + oc];
      v = (v >= 0.f) ? v : 0.1f * v;
      sy[oc * 148 + px] = v;
    }
  }
  __syncthreads();

  float yv[24];
#pragma unroll
  for (int k = 0; k < 24; ++k) yv[k] = sy[k * 148 + px];

#pragma unroll 1
  for (int gl = 0; gl < 6; ++gl) {
    const int g = half * 6 + gl;
    float l9[9];
#pragma unroll
    for (int k9 = 0; k9 < 9; ++k9) {
      const float4* wv = (const float4*)&sw2[(g * 9 + k9) * 24];
      float a = 0.f;
#pragma unroll
      for (int q = 0; q < 6; ++q) {
        const float4 w4 = wv[q];
        a += yv[4 * q] * w4.x + yv[4 * q + 1] * w4.y +
             yv[4 * q + 2] * w4.z + yv[4 * q + 3] * w4.w;
      }
      l9[k9] = a;
    }
    float mx = l9[0];
#pragma unroll
    for (int k = 1; k < 9; ++k) mx = fmaxf(mx, l9[k]);
    float sum = 0.f;
#pragma unroll
    for (int k = 0; k < 9; ++k) { l9[k] = __expf(l9[k] - mx); sum += l9[k]; }
    const float inv = 1.f / sum;
    float s = 0.f;
#pragma unroll
    for (int kh = 0; kh < 3; ++kh)
#pragma unroll
      for (int kw = 0; kw < 3; ++kw)
        s += l9[kh * 3 + kw] * inv * sx[(kh * 12 + g) * 292 + 2 * px + kw];
    out[(size_t)(b * 12 + g) * NPIX + h * 144 + px] = s;
  }
}

// ---------------------------------------------------------------------------
// Cost volumes
// ---------------------------------------------------------------------------
__global__ void gwc_volume(const float* __restrict__ g8x, float* __restrict__ out) {
  __shared__ float lrow[12][WO];
  __shared__ float rrow[12][WO];
  const int h = blockIdx.x, g = blockIdx.y, b = blockIdx.z;
  for (int i = threadIdx.x; i < 12 * WO; i += 256) {
    int c = i / WO, w = i - c * WO;
    size_t base = ((size_t)(b * 96 + g * 12 + c) * HO + h) * WO + w;
    lrow[c][w] = g8x[base];
    rrow[c][w] = g8x[base + (size_t)2 * 96 * NPIX];
  }
  __syncthreads();
  for (int i = threadIdx.x; i < DMAX * WO; i += 256) {
    int d = i / WO, w = i - d * WO;
    float s = 0.f;
    if (w >= d) {
#pragma unroll
      for (int c = 0; c < 12; ++c) s += lrow[c][w] * rrow[c][w - d];
      s *= (1.f / 12.f);
    }
    out[(((size_t)(b * 32 + g) * DMAX + d) * HO + h) * WO + w] = s;
  }
}

__global__ void cat_volume(const float* __restrict__ c8x, float* __restrict__ out) {
  const int idx = blockIdx.x * 256 + threadIdx.x;
  int w = idx % WO;
  int t = idx / WO;
  int hh = t % HO;  t /= HO;
  int d  = t % DMAX; t /= DMAX;
  int c24 = t % 24;
  int b   = t / 24;
  float v = 0.f;
  if (w >= d) {
    if (c24 < 12)
      v = c8x[((size_t)(b * 12 + c24) * HO + hh) * WO + w];
    else
      v = c8x[((size_t)((b + 2) * 12 + (c24 - 12)) * HO + hh) * WO + (w - d)];
  }
  out[(((size_t)(b * 32 + 8 + c24) * DMAX + d) * HO + hh) * WO + w] = v;
}

// ---------------------------------------------------------------------------
// launch
// ---------------------------------------------------------------------------
extern "C" void kernel_launch(void* const* d_in, const int* in_sizes, int n_in,
                              void* d_out, int out_size) {
  const float* gwc_f = (const float*)d_in[0];
  const float* cat_f = (const float*)d_in[1];
  const float* gw1 = (const float*)d_in[2];
  const float* gbg = (const float*)d_in[3];
  const float* gbb = (const float*)d_in[4];
  const float* gbm = (const float*)d_in[5];
  const float* gbv = (const float*)d_in[6];
  const float* gw2 = (const float*)d_in[7];
  const float* cw1 = (const float*)d_in[8];
  const float* cbg = (const float*)d_in[9];
  const float* cbb = (const float*)d_in[10];
  const float* cbm = (const float*)d_in[11];
  const float* cbv = (const float*)d_in[12];
  const float* cw2 = (const float*)d_in[13];
  float* out = (float*)d_out;

  float *y_gwc, *g8x, *c8x, *msk;
  cudaGetSymbolAddress((void**)&y_gwc, g_y_gwc);
  cudaGetSymbolAddress((void**)&g8x,  g_g8x);
  cudaGetSymbolAddress((void**)&c8x,  g_c8x);
  cudaGetSymbolAddress((void**)&msk,  g_mask);

  cudaFuncSetAttribute(conv_mma, cudaFuncAttributeMaxDynamicSharedMemorySize,
                       CONV_SMEM);
  cudaFuncSetAttribute(mask_mma,
                       cudaFuncAttributeMaxDynamicSharedMemorySize, MASK_SMEM);
  cudaFuncSetAttribute(cat_fused,
                       cudaFuncAttributeMaxDynamicSharedMemorySize, CF_SMEM);

  // weight prep (both sets, one launch)
  prep_all<<<(108 * 12 * 32 + 24 * 9 * 32 + 255) / 256, 256>>>(gw1, gw2);

  // gwc branch 96 -> 192 via TF32 mma.sync implicit GEMM
  conv_mma<<<dim3(9, 10, 12), 256, CONV_SMEM>>>(gwc_f, gbg, gbb, gbm, gbv, y_gwc);

  // cat branch fully fused (conv + bn + lrelu + mask + softmax + combine)
  cat_fused<<<dim3(80, 4), 288, CF_SMEM>>>(cat_f, cw1, cbg, cbb, cbm, cbv,
                                           cw2, c8x);

  // gwc mask GEMM + softmax -> masks, then high-occupancy combine
  mask_mma<<<dim3(80, 4), 288, MASK_SMEM>>>(y_gwc, msk);
  combine_gwc<<<dim3(40, 16, 4), 288>>>(gwc_f, msk, g8x);

  // cost volumes straight into d_out
  gwc_volume<<<dim3(HO, 8, 2), 256>>>(g8x, out);
  cat_volume<<<(2 * 24 * DMAX * NPIX) / 256, 256>>>(c8x, out);
}

// round 11
// speedup vs baseline: 1.1201x; 1.1201x over previous
#include <cuda_runtime.h>
#include <cstdint>

// ---------------------------------------------------------------------------
// Problem constants
// ---------------------------------------------------------------------------
static constexpr int H = 160, W = 288, HO = 80, WO = 144;
static constexpr int NPIX = HO * WO;     // 11520
static constexpr int DMAX = 24;          // MAXDISP / (4*S)

// ---------------------------------------------------------------------------
// Scratch (__device__ globals; no cudaMalloc allowed)
// ---------------------------------------------------------------------------
__device__ float g_y_gwc[4 * 192 * NPIX];   // conv1+bn+lrelu output, gwc branch
__device__ float g_g8x[4 * 96 * NPIX];      // downsampled gwc feature
__device__ float g_c8x[4 * 12 * NPIX];      // downsampled concat feature
__device__ float g_mask[4 * 144 * NPIX];    // softmaxed gwc masks [b][g*9+k][px]
// conv1 weights as ready-made m16n8k8 A-fragments:
// [seg = (chunk*9+tap)*4+ks][mtile 0..11][lane 0..31] float4 {a0,a1,a2,a3}
__device__ float4 g_wf[108 * 12 * 32];
// mask conv2 weights as A-fragments: [kstep 0..23][mtile 0..8][lane] float4
__device__ float4 g_w2f[24 * 9 * 32];

// ---------------------------------------------------------------------------
// helpers
// ---------------------------------------------------------------------------
__device__ __forceinline__ uint32_t cvt_tf32(float v) {
  uint32_t t; asm("cvt.rna.tf32.f32 %0, %1;" : "=r"(t) : "f"(v)); return t;
}
__device__ __forceinline__ float cvt_tf32f(float v) {
  return __uint_as_float(cvt_tf32(v));
}
__device__ __forceinline__ void mma8(float* d, const uint32_t* a,
                                     uint32_t b0, uint32_t b1) {
  asm volatile(
      "mma.sync.aligned.m16n8k8.row.col.f32.tf32.tf32.f32 "
      "{%0,%1,%2,%3}, {%4,%5,%6,%7}, {%8,%9}, {%0,%1,%2,%3};"
      : "+f"(d[0]), "+f"(d[1]), "+f"(d[2]), "+f"(d[3])
      : "r"(a[0]), "r"(a[1]), "r"(a[2]), "r"(a[3]), "r"(b0), "r"(b1));
}

// ---------------------------------------------------------------------------
// Weight prep (single launch): conv1 + mask-conv2 fragments, tf32 float4
// ---------------------------------------------------------------------------
__global__ void prep_all(const float* __restrict__ w, const float* __restrict__ w2) {
  int idx = blockIdx.x * 256 + threadIdx.x;
  if (idx < 108 * 12 * 32) {
    int lane = idx & 31;
    int mt   = (idx >> 5) % 12;
    int seg  = idx / (12 * 32);
    int ks   = seg & 3;
    int tile = seg >> 2;            // chunk*9 + tap
    int chunk = tile / 9, tap = tile % 9;
    int lq = lane >> 2, lr = lane & 3;
    int ic = chunk * 32 + ks * 8 + lr;
    int m0 = mt * 16 + lq;
    float4 f;
    f.x = cvt_tf32f(w[((size_t)m0 * 96 + ic) * 9 + tap]);
    f.y = cvt_tf32f(w[((size_t)(m0 + 8) * 96 + ic) * 9 + tap]);
    f.z = cvt_tf32f(w[((size_t)m0 * 96 + ic + 4) * 9 + tap]);
    f.w = cvt_tf32f(w[((size_t)(m0 + 8) * 96 + ic + 4) * 9 + tap]);
    g_wf[idx] = f;
  } else {
    int j = idx - 108 * 12 * 32;
    if (j >= 24 * 9 * 32) return;
    int lane = j & 31;
    int mt   = (j >> 5) % 9;
    int ks   = j / (9 * 32);
    int lq = lane >> 2, lr = lane & 3;
    int k  = ks * 8 + lr;
    int m0 = mt * 16 + lq;
    float4 f;
    f.x = cvt_tf32f(w2[(size_t)m0 * 192 + k]);
    f.y = cvt_tf32f(w2[(size_t)(m0 + 8) * 192 + k]);
    f.z = cvt_tf32f(w2[(size_t)m0 * 192 + k + 4]);
    f.w = cvt_tf32f(w2[(size_t)(m0 + 8) * 192 + k + 4]);
    g_w2f[j] = f;
  }
}

// ---------------------------------------------------------------------------
// TF32 mma.sync implicit-GEMM conv3x3 s2 p1 + BN + LeakyReLU  (96 -> 192)
// Block: 256 threads (8 warps, 2M x 4N). Tile: 64 oc x 128 px (8 rows x 16 cols).
// ---------------------------------------------------------------------------
static constexpr int RAW_WORDS = 17 * 32 * 33;           // 17952 floats
static constexpr int SC_OFF_B  = RAW_WORDS * 4;          // 71808
static constexpr int CONV_SMEM = SC_OFF_B + 2 * 64 * 4;  // 72320

__global__ __launch_bounds__(256, 3)
void conv_mma(const float* __restrict__ x,
              const float* __restrict__ bg, const float* __restrict__ bb,
              const float* __restrict__ bm, const float* __restrict__ bv,
              float* __restrict__ y) {
  extern __shared__ char smem[];
  float* raw = (float*)smem;
  float* sc  = (float*)(smem + SC_OFF_B);
  float* ssh = sc + 64;

  const int tid  = threadIdx.x;
  const int lane = tid & 31;
  const int wid  = tid >> 5;
  const int wm = wid >> 2;          // 0..1
  const int wn = wid & 3;           // 0..3
  const int lq = lane >> 2;         // 0..7
  const int lr = lane & 3;          // 0..3
  const int bx = blockIdx.x, by = blockIdx.y;
  const int b   = blockIdx.z / 3;
  const int ocb = blockIdx.z % 3;
  const int ihb = by * 16 - 1;
  const int iwb = bx * 32 - 1;

  if (tid < 64) {
    const int oc = ocb * 64 + tid;
    const float s = bg[oc] * rsqrtf(bv[oc] + 1e-5f);
    sc[tid]  = s;
    ssh[tid] = bb[oc] - bm[oc] * s;
  }

  float acc[2][4][4];
#pragma unroll
  for (int mi = 0; mi < 2; ++mi)
#pragma unroll
    for (int j = 0; j < 4; ++j)
#pragma unroll
      for (int q = 0; q < 4; ++q) acc[mi][j][q] = 0.f;

  for (int chunk = 0; chunk < 3; ++chunk) {
    __syncthreads();
    // stage raw input (pre-converted to tf32): raw[(ri*32+ic)*33 + ci]
    for (int e = tid; e < 17 * 33 * 32; e += 256) {
      const int ci = e % 33;
      const int t  = e / 33;
      const int ic = t & 31;
      const int ri = t >> 5;
      const int ih = ihb + ri, iw = iwb + ci;
      float v = 0.f;
      if (ih >= 0 && iw >= 0)
        v = x[((size_t)(b * 96 + chunk * 32 + ic) * H + ih) * W + iw];
      raw[(ri * 32 + ic) * 33 + ci] = cvt_tf32f(v);
    }
    __syncthreads();

    for (int tap = 0; tap < 9; ++tap) {
      const int tile = chunk * 9 + tap;
      float4 A4[4][2];
#pragma unroll
      for (int ks = 0; ks < 4; ++ks)
#pragma unroll
        for (int mi = 0; mi < 2; ++mi)
          A4[ks][mi] = __ldg(&g_wf[((size_t)(tile * 4 + ks) * 12 +
                                    ocb * 4 + wm * 2 + mi) * 32 + lane]);
      const int kh = tap / 3, kw = tap % 3;
      int bofs[4];
#pragma unroll
      for (int j = 0; j < 4; ++j) {
        const int ri = 4 * wn + 2 * (j >> 1) + kh;
        const int ci = 16 * (j & 1) + 2 * lq + kw;
        bofs[j] = ri * (32 * 33) + ci;
      }
#pragma unroll
      for (int ks = 0; ks < 4; ++ks) {
        const uint32_t* a0 = reinterpret_cast<const uint32_t*>(&A4[ks][0]);
        const uint32_t* a1 = reinterpret_cast<const uint32_t*>(&A4[ks][1]);
#pragma unroll
        for (int j = 0; j < 4; ++j) {
          const int base = bofs[j] + (ks * 8 + lr) * 33;
          const uint32_t b0 = __float_as_uint(raw[base]);
          const uint32_t b1 = __float_as_uint(raw[base + 4 * 33]);
          mma8(acc[0][j], a0, b0, b1);
          mma8(acc[1][j], a1, b0, b1);
        }
      }
    }
  }

  // epilogue: BN + LeakyReLU, float2 stores into NCHW y
#pragma unroll
  for (int mi = 0; mi < 2; ++mi) {
    const int oc_l0 = wm * 32 + mi * 16 + lq;
    const int oc_l1 = oc_l0 + 8;
    const float s0 = sc[oc_l0], h0 = ssh[oc_l0];
    const float s1 = sc[oc_l1], h1 = ssh[oc_l1];
    const int oc0 = ocb * 64 + oc_l0;
#pragma unroll
    for (int j = 0; j < 4; ++j) {
      const int oh = by * 8 + wn * 2 + (j >> 1);
      const int ow = bx * 16 + (j & 1) * 8 + 2 * lr;
      float v0 = acc[mi][j][0] * s0 + h0;
      float v1 = acc[mi][j][1] * s0 + h0;
      float v2 = acc[mi][j][2] * s1 + h1;
      float v3 = acc[mi][j][3] * s1 + h1;
      v0 = (v0 >= 0.f) ? v0 : 0.1f * v0;
      v1 = (v1 >= 0.f) ? v1 : 0.1f * v1;
      v2 = (v2 >= 0.f) ? v2 : 0.1f * v2;
      v3 = (v3 >= 0.f) ? v3 : 0.1f * v3;
      *(float2*)(y + ((size_t)(b * 192 + oc0)     * HO + oh) * WO + ow) =
          make_float2(v0, v1);
      *(float2*)(y + ((size_t)(b * 192 + oc0 + 8) * HO + oh) * WO + ow) =
          make_float2(v2, v3);
    }
  }
}

// ---------------------------------------------------------------------------
// Mask GEMM (144x192 via mma) + softmax -> normalized masks to gmem.
// One block per (h row, batch): 576 threads (18 warps, 3M x 6N).
// Double-buffered y staging: next chunk's LDGs issue before current chunk's
// mmas, STS after, one sync per chunk -> gmem latency hidden behind tensor
// work; 2 blocks/SM = 36 warps.
// ---------------------------------------------------------------------------
static constexpr int SY_STRIDE = 168;                  // conflict-free b-frags
static constexpr int SY_BUF    = 64 * SY_STRIDE;       // 10752 floats
static constexpr int SL_STRIDE = 145;
static constexpr int MASK_SMEM = 2 * SY_BUF * 4;       // 86016 B (logits alias)

__global__ __launch_bounds__(576, 2)
void mask_mma(const float* __restrict__ y, float* __restrict__ mask) {
  extern __shared__ float smf[];
  float* sybuf[2] = { smf, smf + SY_BUF };
  float* slog = smf;                      // [144][SL_STRIDE] aliases buffers

  const int tid  = threadIdx.x;
  const int lane = tid & 31;
  const int wid  = tid >> 5;              // 0..17
  const int wm = wid / 6, wn = wid % 6;   // 3M x 6N
  const int lq = lane >> 2, lr = lane & 3;
  const int h = blockIdx.x, b = blockIdx.y;

  const float* ybase = y + (size_t)b * 192 * NPIX + h * 144;
  const int s_cc = tid / 144;             // 0..3 (channel offset per j-step)
  const int s_px = tid % 144;

  float facc[3][3][4];
#pragma unroll
  for (int mtl = 0; mtl < 3; ++mtl)
#pragma unroll
    for (int ntl = 0; ntl < 3; ++ntl)
#pragma unroll
      for (int q = 0; q < 4; ++q) facc[mtl][ntl][q] = 0.f;

  float r[16];
  // prologue: load + store chunk 0
#pragma unroll
  for (int j = 0; j < 16; ++j)
    r[j] = cvt_tf32f(ybase[(size_t)(j * 4 + s_cc) * NPIX + s_px]);
#pragma unroll
  for (int j = 0; j < 16; ++j)
    sybuf[0][(j * 4 + s_cc) * SY_STRIDE + s_px] = r[j];
  __syncthreads();

  for (int kc = 0; kc < 3; ++kc) {
    const float* cur = sybuf[kc & 1];
    float* nxt = sybuf[(kc & 1) ^ 1];
    if (kc < 2) {
      const float* ysrc = ybase + (size_t)(kc + 1) * 64 * NPIX;
#pragma unroll
      for (int j = 0; j < 16; ++j)
        r[j] = cvt_tf32f(ysrc[(size_t)(j * 4 + s_cc) * NPIX + s_px]);
    }
#pragma unroll
    for (int ks = 0; ks < 8; ++ks) {
      const int kseg = kc * 8 + ks;
      float4 af[3];
#pragma unroll
      for (int mtl = 0; mtl < 3; ++mtl)
        af[mtl] = __ldg(&g_w2f[((size_t)kseg * 9 + wm * 3 + mtl) * 32 + lane]);
#pragma unroll
      for (int ntl = 0; ntl < 3; ++ntl) {
        const int n0 = (wn * 3 + ntl) * 8;
        const uint32_t b0 =
            __float_as_uint(cur[(ks * 8 + lr) * SY_STRIDE + n0 + lq]);
        const uint32_t b1 =
            __float_as_uint(cur[(ks * 8 + lr + 4) * SY_STRIDE + n0 + lq]);
#pragma unroll
        for (int mtl = 0; mtl < 3; ++mtl)
          mma8(facc[mtl][ntl], reinterpret_cast<const uint32_t*>(&af[mtl]),
               b0, b1);
      }
    }
    if (kc < 2) {
#pragma unroll
      for (int j = 0; j < 16; ++j)
        nxt[(j * 4 + s_cc) * SY_STRIDE + s_px] = r[j];
    }
    __syncthreads();
  }

  // write raw logits to smem (aliases buffers; all compute done)
#pragma unroll
  for (int mtl = 0; mtl < 3; ++mtl) {
    const int m0 = (wm * 3 + mtl) * 16;
#pragma unroll
    for (int ntl = 0; ntl < 3; ++ntl) {
      const int n0 = (wn * 3 + ntl) * 8 + 2 * lr;
      slog[(m0 + lq)     * SL_STRIDE + n0]     = facc[mtl][ntl][0];
      slog[(m0 + lq)     * SL_STRIDE + n0 + 1] = facc[mtl][ntl][1];
      slog[(m0 + lq + 8) * SL_STRIDE + n0]     = facc[mtl][ntl][2];
      slog[(m0 + lq + 8) * SL_STRIDE + n0 + 1] = facc[mtl][ntl][3];
    }
  }
  __syncthreads();

  // softmax + write masks: thread owns px = tid%144; groups g = tid/144 + 4*i
  const int px = s_px;
  const int gh = s_cc;               // 0..3
#pragma unroll
  for (int i = 0; i < 4; ++i) {
    const int g = gh + 4 * i;
    float m9[9];
#pragma unroll
    for (int k = 0; k < 9; ++k) m9[k] = slog[(g * 9 + k) * SL_STRIDE + px];
    float mx = m9[0];
#pragma unroll
    for (int k = 1; k < 9; ++k) mx = fmaxf(mx, m9[k]);
    float sum = 0.f;
#pragma unroll
    for (int k = 0; k < 9; ++k) { m9[k] = __expf(m9[k] - mx); sum += m9[k]; }
    const float inv = 1.f / sum;
#pragma unroll
    for (int k = 0; k < 9; ++k)
      mask[((size_t)(b * 16 + g) * 9 + k) * NPIX + h * 144 + px] = m9[k] * inv;
  }
}

// ---------------------------------------------------------------------------
// Combine: out[b][cc*16+g][h][px] = sum_k mask[b][g*9+k][h][px] * x_window.
// Grid (40 h-pairs, 16 g, 4 b) = 2560 blocks, 288 thr, 10.4 KB smem.
// ---------------------------------------------------------------------------
__global__ __launch_bounds__(288)
void combine_gwc(const float* __restrict__ x, const float* __restrict__ mask,
                 float* __restrict__ out) {
  __shared__ float smk[2 * 9 * 144];
  const int tid = threadIdx.x;
  const int g = blockIdx.y, b = blockIdx.z;
  const int h0 = blockIdx.x * 2;

  const size_t mbase = ((size_t)(b * 16 + g) * 9) * NPIX + h0 * 144;
  for (int i = tid; i < 2 * 9 * 144; i += 288) {
    const int hloc = i / (9 * 144);
    const int rem  = i - hloc * (9 * 144);       // k*144 + px
    const int k    = rem / 144;
    const int px   = rem - k * 144;
    smk[i] = mask[mbase + (size_t)k * NPIX + hloc * 144 + px];
  }
  __syncthreads();

  const int px   = tid % 144;
  const int hloc = tid / 144;
  const int h = h0 + hloc;

  float mk[9];
#pragma unroll
  for (int k = 0; k < 9; ++k) mk[k] = smk[hloc * 9 * 144 + k * 144 + px];

#pragma unroll 2
  for (int cc = 0; cc < 6; ++cc) {
    const int c = cc * 16 + g;
    const float* xb = x + (size_t)(b * 96 + c) * H * W;
    float s = 0.f;
#pragma unroll
    for (int kh = 0; kh < 3; ++kh) {
      const int ih = 2 * h - 1 + kh;
      if ((unsigned)ih >= (unsigned)H) continue;
#pragma unroll
      for (int kw = 0; kw < 3; ++kw) {
        const int iw = 2 * px - 1 + kw;
        if ((unsigned)iw >= (unsigned)W) continue;
        s += mk[kh * 3 + kw] * __ldg(&xb[(size_t)ih * W + iw]);
      }
    }
    out[(size_t)(b * 96 + c) * NPIX + h * 144 + px] = s;
  }
}

// ---------------------------------------------------------------------------
// Fully fused cat branch (unchanged)
// ---------------------------------------------------------------------------
static constexpr int CF_SX   = 0;                       // [3][12][292] floats
static constexpr int CF_SY   = 3 * 12 * 292;            // 10512 -> [24][148]
static constexpr int CF_SW1  = CF_SY + 24 * 148;        // [108][24]
static constexpr int CF_SW2  = CF_SW1 + 108 * 24;       // [108][24] (m-major)
static constexpr int CF_SBN  = CF_SW2 + 108 * 24;       // [2][24]
static constexpr int CF_SMEM = (CF_SBN + 48) * 4;       // ~77 KB

__global__ __launch_bounds__(288, 2)
void cat_fused(const float* __restrict__ x, const float* __restrict__ w1,
               const float* __restrict__ bg, const float* __restrict__ bb,
               const float* __restrict__ bm, const float* __restrict__ bv,
               const float* __restrict__ w2, float* __restrict__ out) {
  extern __shared__ float sm[];
  float* sx  = sm + CF_SX;    // [kh][ic][iw+1], zero-padded
  float* sy  = sm + CF_SY;    // [oc][px]
  float* sw1 = sm + CF_SW1;   // [ic*9+tap][oc]
  float* sw2 = sm + CF_SW2;   // [mask][k]
  float* sbn = sm + CF_SBN;

  const int tid = threadIdx.x;
  const int h = blockIdx.x, b = blockIdx.y;

  for (int i = tid; i < 24 * 108; i += 288) {
    const int oc = i / 108, rem = i - oc * 108;   // rem = ic*9 + tap
    sw1[rem * 24 + oc] = w1[i];
  }
  for (int i = tid; i < 108 * 24; i += 288) sw2[i] = w2[i];
  if (tid < 24) {
    const float s = bg[tid] * rsqrtf(bv[tid] + 1e-5f);
    sbn[tid]      = s;
    sbn[24 + tid] = bb[tid] - bm[tid] * s;
  }
  for (int i = tid; i < 3 * 12 * 290; i += 288) {
    const int r  = i / (12 * 290);
    const int rem = i - r * (12 * 290);
    const int c  = rem / 290;
    const int iw = rem - c * 290 - 1;
    const int ih = 2 * h - 1 + r;
    float v = 0.f;
    if ((unsigned)ih < (unsigned)H && (unsigned)iw < (unsigned)W)
      v = x[((size_t)(b * 12 + c) * H + ih) * W + iw];
    sx[(r * 12 + c) * 292 + iw + 1] = v;
  }
  __syncthreads();

  const int px   = tid % 144;
  const int half = tid / 144;

  {
    float acc[12];
#pragma unroll
    for (int o = 0; o < 12; ++o) acc[o] = 0.f;
#pragma unroll 3
    for (int ic = 0; ic < 12; ++ic) {
#pragma unroll
      for (int kh = 0; kh < 3; ++kh) {
#pragma unroll
        for (int kw = 0; kw < 3; ++kw) {
          const float xv = sx[(kh * 12 + ic) * 292 + 2 * px + kw];
          const float* wr = &sw1[(ic * 9 + kh * 3 + kw) * 24 + half * 12];
          const float4 wa = *(const float4*)(wr);
          const float4 wb = *(const float4*)(wr + 4);
          const float4 wc = *(const float4*)(wr + 8);
          acc[0] += xv * wa.x; acc[1] += xv * wa.y;
          acc[2] += xv * wa.z; acc[3] += xv * wa.w;
          acc[4] += xv * wb.x; acc[5] += xv * wb.y;
          acc[6] += xv * wb.z; acc[7] += xv * wb.w;
          acc[8] += xv * wc.x; acc[9] += xv * wc.y;
          acc[10] += xv * wc.z; acc[11] += xv * wc.w;
        }
      }
    }
#pragma unroll
    for (int o = 0; o < 12; ++o) {
      const int oc = half * 12 + o;
      float v = acc[o] * sbn[oc] + sbn[24 + oc];
      v = (v >= 0.f) ? v : 0.1f * v;
      sy[oc * 148 + px] = v;
    }
  }
  __syncthreads();

  float yv[24];
#pragma unroll
  for (int k = 0; k < 24; ++k) yv[k] = sy[k * 148 + px];

#pragma unroll 1
  for (int gl = 0; gl < 6; ++gl) {
    const int g = half * 6 + gl;
    float l9[9];
#pragma unroll
    for (int k9 = 0; k9 < 9; ++k9) {
      const float4* wv = (const float4*)&sw2[(g * 9 + k9) * 24];
      float a = 0.f;
#pragma unroll
      for (int q = 0; q < 6; ++q) {
        const float4 w4 = wv[q];
        a += yv[4 * q] * w4.x + yv[4 * q + 1] * w4.y +
             yv[4 * q + 2] * w4.z + yv[4 * q + 3] * w4.w;
      }
      l9[k9] = a;
    }
    float mx = l9[0];
#pragma unroll
    for (int k = 1; k < 9; ++k) mx = fmaxf(mx, l9[k]);
    float sum = 0.f;
#pragma unroll
    for (int k = 0; k < 9; ++k) { l9[k] = __expf(l9[k] - mx); sum += l9[k]; }
    const float inv = 1.f / sum;
    float s = 0.f;
#pragma unroll
    for (int kh = 0; kh < 3; ++kh)
#pragma unroll
      for (int kw = 0; kw < 3; ++kw)
        s += l9[kh * 3 + kw] * inv * sx[(kh * 12 + g) * 292 + 2 * px + kw];
    out[(size_t)(b * 12 + g) * NPIX + h * 144 + px] = s;
  }
}

// ---------------------------------------------------------------------------
// Cost volumes
// ---------------------------------------------------------------------------
__global__ void gwc_volume(const float* __restrict__ g8x, float* __restrict__ out) {
  __shared__ float lrow[12][WO];
  __shared__ float rrow[12][WO];
  const int h = blockIdx.x, g = blockIdx.y, b = blockIdx.z;
  for (int i = threadIdx.x; i < 12 * WO; i += 256) {
    int c = i / WO, w = i - c * WO;
    size_t base = ((size_t)(b * 96 + g * 12 + c) * HO + h) * WO + w;
    lrow[c][w] = g8x[base];
    rrow[c][w] = g8x[base + (size_t)2 * 96 * NPIX];
  }
  __syncthreads();
  for (int i = threadIdx.x; i < DMAX * WO; i += 256) {
    int d = i / WO, w = i - d * WO;
    float s = 0.f;
    if (w >= d) {
#pragma unroll
      for (int c = 0; c < 12; ++c) s += lrow[c][w] * rrow[c][w - d];
      s *= (1.f / 12.f);
    }
    out[(((size_t)(b * 32 + g) * DMAX + d) * HO + h) * WO + w] = s;
  }
}

__global__ void cat_volume(const float* __restrict__ c8x, float* __restrict__ out) {
  const int idx = blockIdx.x * 256 + threadIdx.x;
  int w = idx % WO;
  int t = idx / WO;
  int hh = t % HO;  t /= HO;
  int d  = t % DMAX; t /= DMAX;
  int c24 = t % 24;
  int b   = t / 24;
  float v = 0.f;
  if (w >= d) {
    if (c24 < 12)
      v = c8x[((size_t)(b * 12 + c24) * HO + hh) * WO + w];
    else
      v = c8x[((size_t)((b + 2) * 12 + (c24 - 12)) * HO + hh) * WO + (w - d)];
  }
  out[(((size_t)(b * 32 + 8 + c24) * DMAX + d) * HO + hh) * WO + w] = v;
}

// ---------------------------------------------------------------------------
// launch
// ---------------------------------------------------------------------------
extern "C" void kernel_launch(void* const* d_in, const int* in_sizes, int n_in,
                              void* d_out, int out_size) {
  const float* gwc_f = (const float*)d_in[0];
  const float* cat_f = (const float*)d_in[1];
  const float* gw1 = (const float*)d_in[2];
  const float* gbg = (const float*)d_in[3];
  const float* gbb = (const float*)d_in[4];
  const float* gbm = (const float*)d_in[5];
  const float* gbv = (const float*)d_in[6];
  const float* gw2 = (const float*)d_in[7];
  const float* cw1 = (const float*)d_in[8];
  const float* cbg = (const float*)d_in[9];
  const float* cbb = (const float*)d_in[10];
  const float* cbm = (const float*)d_in[11];
  const float* cbv = (const float*)d_in[12];
  const float* cw2 = (const float*)d_in[13];
  float* out = (float*)d_out;

  float *y_gwc, *g8x, *c8x, *msk;
  cudaGetSymbolAddress((void**)&y_gwc, g_y_gwc);
  cudaGetSymbolAddress((void**)&g8x,  g_g8x);
  cudaGetSymbolAddress((void**)&c8x,  g_c8x);
  cudaGetSymbolAddress((void**)&msk,  g_mask);

  cudaFuncSetAttribute(conv_mma, cudaFuncAttributeMaxDynamicSharedMemorySize,
                       CONV_SMEM);
  cudaFuncSetAttribute(mask_mma,
                       cudaFuncAttributeMaxDynamicSharedMemorySize, MASK_SMEM);
  cudaFuncSetAttribute(cat_fused,
                       cudaFuncAttributeMaxDynamicSharedMemorySize, CF_SMEM);

  // weight prep (both sets, one launch)
  prep_all<<<(108 * 12 * 32 + 24 * 9 * 32 + 255) / 256, 256>>>(gw1, gw2);

  // gwc branch 96 -> 192 via TF32 mma.sync implicit GEMM
  conv_mma<<<dim3(9, 10, 12), 256, CONV_SMEM>>>(gwc_f, gbg, gbb, gbm, gbv, y_gwc);

  // cat branch fully fused (conv + bn + lrelu + mask + softmax + combine)
  cat_fused<<<dim3(80, 4), 288, CF_SMEM>>>(cat_f, cw1, cbg, cbb, cbm, cbv,
                                           cw2, c8x);

  // gwc mask GEMM + softmax -> masks, then high-occupancy combine
  mask_mma<<<dim3(80, 4), 576, MASK_SMEM>>>(y_gwc, msk);
  combine_gwc<<<dim3(40, 16, 4), 288>>>(gwc_f, msk, g8x);

  // cost volumes straight into d_out
  gwc_volume<<<dim3(HO, 8, 2), 256>>>(g8x, out);
  cat_volume<<<(2 * 24 * DMAX * NPIX) / 256, 256>>>(c8x, out);
}